// round 15
// baseline (speedup 1.0000x reference)
#include <cuda_runtime.h>
#include <math.h>

#define NN   1024
#define BB   16
#define NPIX (NN*NN)
#define BPB  64      // blocks per batch (grid 1024 total — all co-resident)
#define TPB  256
#define NITER 8      // phase 1: NPIX/8 / (BPB*TPB)  (8 floats/thread/iter)
#define NBLK (BPB*BB)
#define C_NIT 16     // phase 2: (NPIX/4) / (BPB*TPB)

// radius = 1/N^2/2 = 2^-21, exactly representable
#define RADIUS (4.76837158203125e-07f)

__device__ float              g_pm[BB][BPB];   // partial max (masked saliency)
__device__ unsigned long long g_pk[BB][BPB];   // partial key (d_bits<<20 | idx)
__device__ unsigned           g_any[BB*BPB];
__device__ unsigned           g_ctr = 0;       // barrier arrivals
__device__ unsigned           g_release = 0;   // barrier release flag
__device__ unsigned           g_done = 0;      // epilogue reset counter
__device__ int                g_anyflag;
__device__ float              g_loc[BB][4];    // lx, ly, eps

// 32-byte L2 evict-last load: keeps hist resident in L2 for phase 2.
__device__ __forceinline__ void ldg_evict_last8(const float* p, float* v) {
    asm volatile("ld.global.L2::evict_last.v8.b32 {%0,%1,%2,%3,%4,%5,%6,%7}, [%8];"
                 : "=f"(v[0]), "=f"(v[1]), "=f"(v[2]), "=f"(v[3]),
                   "=f"(v[4]), "=f"(v[5]), "=f"(v[6]), "=f"(v[7])
                 : "l"(p));
}

__device__ __forceinline__ void upd_cand(float m, unsigned long long k,
                                         float& bm, unsigned long long& bk) {
    bool u = (m > bm) || (m == bm && k < bk);
    if (u) { bm = m; bk = k; }
}

// finalize one batch; writer thread fences to gpu scope afterwards
__device__ __forceinline__ void finalize_batch(
    int b, float bm, unsigned long long bk,
    const float* __restrict__ sal, const float* __restrict__ cur,
    const float* __restrict__ r, float* __restrict__ out)
{
    bool allz = (bm == 0.0f);          // masked >= 0 always
    int idx;
    float salv;
    if (allz) {
        idx = 0;                        // argmin of all-inf d -> index 0
        float dx = r[0] - cur[2*b], dyv = r[0] - cur[2*b+1];
        float d00 = __fmul_rn(__fadd_rn(__fmul_rn(dx,dx), __fmul_rn(dyv,dyv)), 0.5f);
        salv = (d00 <= RADIUS) ? 0.0f : sal[(size_t)b * NPIX];
    } else {
        idx  = (int)(bk & 0xFFFFFu);
        salv = sal[(size_t)b * NPIX + idx];   // m>0 => not cur-masked
    }
    int py = idx >> 10, px = idx & 1023;
    float lx = 2.0f * ((float)(px + 1) / 1024.0f) - 1.0f;
    float ly = 2.0f * ((float)(py + 1) / 1024.0f) - 1.0f;
    float sm  = fmaxf(salv, 1e-4f);
    float eps = 10.0f / sm;
    out[2*b]     = allz ? 1.0f : lx;
    out[2*b + 1] = allz ? 1.0f : ly;
    g_loc[b][0] = lx; g_loc[b][1] = ly; g_loc[b][2] = eps;
    __threadfence();                    // gpu-scope: visible to spinning blocks
}

// ---------------------------------------------------------------------------
// Fused kernel: phase 1 = argmax scan (hist pinned in L2, sal streamed),
// software grid barrier (all 1024 blocks co-resident at 8 CTA/SM), last block
// finalizes, phase 2 = RBF mask + hist update with hist re-read from L2.
// ---------------------------------------------------------------------------
__global__ void __launch_bounds__(TPB, 8)
kernelFused(const float* __restrict__ sal, const float* __restrict__ hist,
            const float* __restrict__ cur, const float* __restrict__ grid,
            float* __restrict__ out)
{
    __shared__ __align__(16) float r[NN];
    __shared__ float              red_m[TPB];
    __shared__ unsigned long long red_k[TPB];
    __shared__ unsigned           sh_max;
    __shared__ int                lastBlk;

    const int b   = blockIdx.y;
    const int tid = threadIdx.x;

    if (tid == 0) sh_max = 0u;
    for (int i = tid; i < NN; i += TPB) r[i] = grid[2*i];
    __syncthreads();

    const float cx = cur[2*b], cy = cur[2*b+1];
    const float* salb = sal  + (size_t)b * NPIX;
    const float* hb   = hist + (size_t)b * NPIX;

    float bm = -1.0f; unsigned long long bk = ~0ull;
    unsigned acc = 0u;

    const int base = blockIdx.x * TPB + tid;
    #pragma unroll 4
    for (int it = 0; it < NITER; it++) {
        int p0 = (base + it * (BPB * TPB)) * 8;
        float hv[8];
        ldg_evict_last8(hb + p0, hv);                    // hist: pin in L2
        float4 sa = __ldcs((const float4*)(salb + p0));  // sal: evict-first
        float4 sb = __ldcs((const float4*)(salb + p0 + 4));
        float sv[8] = {sa.x, sa.y, sa.z, sa.w, sb.x, sb.y, sb.z, sb.w};

        unsigned ao = 0u;
        float m8 = 0.0f;
        #pragma unroll
        for (int j = 0; j < 8; j++) {
            ao |= __float_as_uint(hv[j]);
            m8 = fmaxf(m8, __fmul_rn(hv[j], sv[j]));
        }
        acc |= ao;
        unsigned stale = sh_max;                    // stale = lower bound
        if (__float_as_uint(m8) >= stale) {         // rare after warmup
            int y = p0 >> 10, x = p0 & 1023;
            float dy  = r[y] - cy;
            float dy2 = __fmul_rn(dy, dy);
            float4 ga = *(const float4*)&r[x];
            float4 gb = *(const float4*)&r[x + 4];
            float gx[8] = {ga.x, ga.y, ga.z, ga.w, gb.x, gb.y, gb.z, gb.w};
            #pragma unroll
            for (int j = 0; j < 8; j++) {
                float dx = gx[j] - cx;
                float d  = __fmul_rn(__fadd_rn(__fmul_rn(dx, dx), dy2), 0.5f);
                float s  = (d <= RADIUS) ? 0.0f : sv[j];
                float mh = __fmul_rn(hv[j], s);
                unsigned long long key =
                    ((unsigned long long)__float_as_uint(d) << 20) | (unsigned)(p0 + j);
                upd_cand(mh, key, bm, bk);
            }
            if (bm > 0.0f) atomicMax(&sh_max, __float_as_uint(bm));
        }
    }

    red_m[tid] = bm; red_k[tid] = bk;
    int anyv = __syncthreads_or((acc << 1) != 0u);   // <<1 kills -0 sign bits
    for (int w = TPB / 2; w > 0; w >>= 1) {
        if (tid < w) upd_cand(red_m[tid + w], red_k[tid + w], red_m[tid], red_k[tid]);
        __syncthreads();
    }
    if (tid == 0) {
        g_pm[b][blockIdx.x] = red_m[0];
        g_pk[b][blockIdx.x] = red_k[0];
        g_any[b * BPB + blockIdx.x] = anyv ? 1u : 0u;
        __threadfence();
        unsigned old = atomicAdd(&g_ctr, 1u);
        lastBlk = (old == (unsigned)(NBLK - 1));
    }
    __syncthreads();

    if (lastBlk) {
        // ---- finalization (was kernelB) ----
        unsigned a = 0;
        for (int i = tid; i < BB * BPB; i += TPB) a |= g_any[i];
        int anyAll = __syncthreads_or(a != 0u);
        if (tid == 0) { g_anyflag = anyAll; __threadfence(); }

        if (anyAll) {
            const int warp = tid >> 5, lane = tid & 31;
            for (int bb = warp; bb < BB; bb += 8) {
                float fm = -1.0f; unsigned long long fk = ~0ull;
                for (int i = lane; i < BPB; i += 32)
                    upd_cand(g_pm[bb][i], g_pk[bb][i], fm, fk);
                #pragma unroll
                for (int o = 16; o > 0; o >>= 1) {
                    float m2              = __shfl_xor_sync(0xffffffffu, fm, o);
                    unsigned long long k2 = __shfl_xor_sync(0xffffffffu, fk, o);
                    upd_cand(m2, k2, fm, fk);
                }
                if (lane == 0) finalize_batch(bb, fm, fk, sal, cur, r, out);
            }
        } else {
            // degenerate: whole hist zero -> treated as ones (never taken here)
            for (int bb = 0; bb < BB; bb++) {
                const float bx = cur[2*bb], by = cur[2*bb+1];
                float fm = -1.0f; unsigned long long fk = ~0ull;
                for (int p = tid; p < NPIX; p += TPB) {
                    int y = p >> 10, x = p & 1023;
                    float dx = r[x] - bx, dyv = r[y] - by;
                    float d  = __fmul_rn(__fadd_rn(__fmul_rn(dx, dx), __fmul_rn(dyv, dyv)), 0.5f);
                    float s  = (d <= RADIUS) ? 0.0f : sal[(size_t)bb * NPIX + p];
                    unsigned long long key =
                        ((unsigned long long)__float_as_uint(d) << 20) | (unsigned)p;
                    upd_cand(s, key, fm, fk);
                }
                red_m[tid] = fm; red_k[tid] = fk;
                __syncthreads();
                for (int w = TPB / 2; w > 0; w >>= 1) {
                    if (tid < w) upd_cand(red_m[tid + w], red_k[tid + w], red_m[tid], red_k[tid]);
                    __syncthreads();
                }
                if (tid == 0) finalize_batch(bb, red_m[0], red_k[0], sal, cur, r, out);
                __syncthreads();
            }
        }
        __syncthreads();
        if (tid == 0) { __threadfence(); atomicExch(&g_release, 1u); }
    } else {
        // spin until finalization is published (all blocks co-resident: safe)
        if (tid == 0) {
            while (atomicAdd(&g_release, 0u) == 0u) __nanosleep(128);
        }
    }
    __syncthreads();
    __threadfence();   // acquire ordering for g_loc / g_anyflag reads

    // ---- phase 2 (was kernelC): hist re-read hits L2 ----
    const float lx = g_loc[b][0], ly = g_loc[b][1], eps = g_loc[b][2];
    const int anyh = g_anyflag;

    const float4* h4p = (const float4*)hb;
    float4* hout = (float4*)(out + 32 + (size_t)b * NPIX);
    float4* mout = (float4*)(out + 32 + (size_t)BB * NPIX + (size_t)b * NPIX);

    #pragma unroll 4
    for (int it = 0; it < C_NIT; it++) {
        int v = base + it * (BPB * TPB);
        float4 h = __ldcs(&h4p[v]);     // last consumer: evict-first
        if (!anyh) h = make_float4(1.f, 1.f, 1.f, 1.f);
        int p0 = v * 4;
        int y = p0 >> 10, x = p0 & 1023;
        float dyl = r[y] - ly;
        float dy2 = __fmul_rn(dyl, dyl);
        float4 gx4 = *(const float4*)&r[x];
        float gx[4] = {gx4.x, gx4.y, gx4.z, gx4.w};
        float hv[4] = {h.x, h.y, h.z, h.w};
        float m[4], ho[4];
        #pragma unroll
        for (int j = 0; j < 4; j++) {
            float dx  = gx[j] - lx;
            float rbf = __fmul_rn(__fadd_rn(__fmul_rn(dx, dx), dy2), 0.5f);
            float t   = __fmul_rn(rbf, eps);
            float mm  = __expf(-__fmul_rn(t, t));
            m[j] = mm;
            ho[j] = __saturatef(__fmul_rn(hv[j], 1.0f - mm));
        }
        __stcs(&hout[v], make_float4(ho[0], ho[1], ho[2], ho[3]));
        __stcs(&mout[v], make_float4(m[0],  m[1],  m[2],  m[3]));
    }

    // ---- epilogue: reset barrier state for the next graph replay.
    // Only runs after ALL blocks incremented g_done, i.e. after every block
    // observed g_release==1 — no lost-wakeup possible.
    if (tid == 0) {
        unsigned o = atomicAdd(&g_done, 1u);
        if (o == (unsigned)(NBLK - 1)) {
            g_ctr = 0; g_release = 0; g_done = 0;
        }
    }
}

extern "C" void kernel_launch(void* const* d_in, const int* in_sizes, int n_in,
                              void* d_out, int out_size)
{
    (void)in_sizes; (void)n_in; (void)out_size;
    const float* sal  = (const float*)d_in[0];  // (16,1024,1024)
    const float* hist = (const float*)d_in[1];  // (16,1,1024,1024)
    const float* cur  = (const float*)d_in[2];  // (16,2)
    const float* grid = (const float*)d_in[3];  // (1024,1024,2)
    float* out = (float*)d_out;                 // 32 + 16M (hist) + 16M (mask)

    kernelFused<<<dim3(BPB, BB), TPB>>>(sal, hist, cur, grid, out);
}

// round 16
// speedup vs baseline: 1.0164x; 1.0164x over previous
#include <cuda_runtime.h>
#include <math.h>

#define NN   1024
#define BB   16
#define NPIX (NN*NN)
#define BPB  64      // blocks per batch, kernel A (grid 1024 — proven best)
#define TPB  256
#define NITER 16     // NPIX/4 / (BPB*TPB)

// radius = 1/N^2/2 = 2^-21, exactly representable
#define RADIUS (4.76837158203125e-07f)

__device__ float              g_pm[BB][BPB];   // partial max (masked saliency)
__device__ unsigned long long g_pk[BB][BPB];   // partial key (d_bits<<20 | idx)
__device__ unsigned           g_any[BB*BPB];
__device__ unsigned           g_ctr = 0;
__device__ int                g_anyflag;
__device__ float              g_loc[BB][4];    // lx, ly, eps

// 256-bit global store (sm_103a STG.256): halves C's store instruction count.
__device__ __forceinline__ void stg8(float* p, const float* v) {
    asm volatile("st.global.v8.b32 [%0], {%1,%2,%3,%4,%5,%6,%7,%8};"
                 :: "l"(p), "f"(v[0]), "f"(v[1]), "f"(v[2]), "f"(v[3]),
                    "f"(v[4]), "f"(v[5]), "f"(v[6]), "f"(v[7]) : "memory");
}

__device__ __forceinline__ void upd_cand(float m, unsigned long long k,
                                         float& bm, unsigned long long& bk) {
    bool u = (m > bm) || (m == bm && k < bk);
    if (u) { bm = m; bk = k; }
}

// finalize one batch: compute next_xy + (lx,ly,eps) from the winning candidate
__device__ __forceinline__ void finalize_batch(
    int b, float bm, unsigned long long bk,
    const float* __restrict__ sal, const float* __restrict__ cur,
    const float* __restrict__ r, float* __restrict__ out)
{
    bool allz = (bm == 0.0f);          // masked >= 0 always
    int idx;
    float salv;
    if (allz) {
        idx = 0;                        // argmin of all-inf d -> index 0
        float dx = r[0] - cur[2*b], dyv = r[0] - cur[2*b+1];
        float d00 = __fmul_rn(__fadd_rn(__fmul_rn(dx,dx), __fmul_rn(dyv,dyv)), 0.5f);
        salv = (d00 <= RADIUS) ? 0.0f : sal[(size_t)b * NPIX];
    } else {
        idx  = (int)(bk & 0xFFFFFu);
        salv = sal[(size_t)b * NPIX + idx];   // m>0 => not cur-masked
    }
    int py = idx >> 10, px = idx & 1023;
    float lx = 2.0f * ((float)(px + 1) / 1024.0f) - 1.0f;
    float ly = 2.0f * ((float)(py + 1) / 1024.0f) - 1.0f;
    float sm  = fmaxf(salv, 1e-4f);
    float eps = 10.0f / sm;
    out[2*b]     = allz ? 1.0f : lx;
    out[2*b + 1] = allz ? 1.0f : ly;
    g_loc[b][0] = lx; g_loc[b][1] = ly; g_loc[b][2] = eps;
}

// ---------------------------------------------------------------------------
// Kernel A (R12 form — proven best): fused { cur-mask, masked=hist*sal,
// (max,key) reduce, any-OR }; block-wide shared-max gate (stale read = lower
// bound of final block max, so skipped elements can neither win nor tie).
// Last block (atomic ticket) finalizes + degenerate hist-all-zero fallback.
// ---------------------------------------------------------------------------
__global__ void __launch_bounds__(TPB, 8)
kernelA(const float* __restrict__ sal, const float* __restrict__ hist,
        const float* __restrict__ cur, const float* __restrict__ grid,
        float* __restrict__ out)
{
    cudaTriggerProgrammaticLaunchCompletion();

    __shared__ __align__(16) float r[NN];
    __shared__ float              red_m[TPB];
    __shared__ unsigned long long red_k[TPB];
    __shared__ unsigned           sh_max;      // block running max (float bits, >=0)
    __shared__ int                lastBlk;

    const int b   = blockIdx.y;
    const int tid = threadIdx.x;

    if (tid == 0) sh_max = 0u;
    for (int i = tid; i < NN; i += TPB) r[i] = grid[2*i];
    __syncthreads();

    const float cx = cur[2*b], cy = cur[2*b+1];
    const float4* sal4 = (const float4*)(sal  + (size_t)b * NPIX);
    const float4* h4p  = (const float4*)(hist + (size_t)b * NPIX);

    float bm = -1.0f; unsigned long long bk = ~0ull;
    unsigned acc = 0u;

    const int base = blockIdx.x * TPB + tid;
    #pragma unroll 4
    for (int it = 0; it < NITER; it++) {
        int v = base + it * (BPB * TPB);
        float4 s4 = __ldcs(&sal4[v]);   // sal never reused -> evict-first
        float4 h4 = h4p[v];             // hist reused by kernelC -> keep in L2
        acc |= (__float_as_uint(h4.x) | __float_as_uint(h4.y) |
                __float_as_uint(h4.z) | __float_as_uint(h4.w));
        float m0 = __fmul_rn(h4.x, s4.x);
        float m1 = __fmul_rn(h4.y, s4.y);
        float m2 = __fmul_rn(h4.z, s4.z);
        float m3 = __fmul_rn(h4.w, s4.w);
        float m4 = fmaxf(fmaxf(m0, m1), fmaxf(m2, m3));
        unsigned stale = sh_max;                    // may be stale: lower bound
        if (__float_as_uint(m4) >= stale) {         // rare after warmup
            int p0 = v * 4;
            int y = p0 >> 10, x = p0 & 1023;
            float dy  = r[y] - cy;
            float dy2 = __fmul_rn(dy, dy);
            float4 gx4 = *(const float4*)&r[x];
            float gx[4] = {gx4.x, gx4.y, gx4.z, gx4.w};
            float sv[4] = {s4.x, s4.y, s4.z, s4.w};
            float hv[4] = {h4.x, h4.y, h4.z, h4.w};
            #pragma unroll
            for (int j = 0; j < 4; j++) {
                float dx = gx[j] - cx;
                float d  = __fmul_rn(__fadd_rn(__fmul_rn(dx, dx), dy2), 0.5f);
                float s  = (d <= RADIUS) ? 0.0f : sv[j];
                float mh = __fmul_rn(hv[j], s);
                unsigned long long key =
                    ((unsigned long long)__float_as_uint(d) << 20) | (unsigned)(p0 + j);
                upd_cand(mh, key, bm, bk);
            }
            if (bm > 0.0f) atomicMax(&sh_max, __float_as_uint(bm));
        }
    }

    red_m[tid] = bm; red_k[tid] = bk;
    int anyv = __syncthreads_or((acc << 1) != 0u);   // <<1 kills -0 sign bits
    for (int w = TPB / 2; w > 0; w >>= 1) {
        if (tid < w) upd_cand(red_m[tid + w], red_k[tid + w], red_m[tid], red_k[tid]);
        __syncthreads();
    }
    if (tid == 0) {
        g_pm[b][blockIdx.x] = red_m[0];
        g_pk[b][blockIdx.x] = red_k[0];
        g_any[b * BPB + blockIdx.x] = anyv ? 1u : 0u;
        __threadfence();
        unsigned old = atomicAdd(&g_ctr, 1u);
        lastBlk = (old == (unsigned)(BPB * BB - 1));
    }
    __syncthreads();
    if (!lastBlk) return;

    // ---- last block: finalization ----
    unsigned a = 0;
    for (int i = tid; i < BB * BPB; i += TPB) a |= g_any[i];
    int anyAll = __syncthreads_or(a != 0u);
    if (tid == 0) { g_anyflag = anyAll; g_ctr = 0; }

    if (anyAll) {
        const int warp = tid >> 5, lane = tid & 31;
        for (int bb = warp; bb < BB; bb += 8) {
            float fm = -1.0f; unsigned long long fk = ~0ull;
            for (int i = lane; i < BPB; i += 32)
                upd_cand(g_pm[bb][i], g_pk[bb][i], fm, fk);
            #pragma unroll
            for (int o = 16; o > 0; o >>= 1) {
                float m2              = __shfl_xor_sync(0xffffffffu, fm, o);
                unsigned long long k2 = __shfl_xor_sync(0xffffffffu, fk, o);
                upd_cand(m2, k2, fm, fk);
            }
            if (lane == 0) finalize_batch(bb, fm, fk, sal, cur, r, out);
        }
    } else {
        // degenerate: whole hist tensor is zero -> hist treated as ones.
        // Slow block-local rescan; never taken for this input, correctness only.
        for (int bb = 0; bb < BB; bb++) {
            const float bx = cur[2*bb], by = cur[2*bb+1];
            float fm = -1.0f; unsigned long long fk = ~0ull;
            for (int p = tid; p < NPIX; p += TPB) {
                int y = p >> 10, x = p & 1023;
                float dx = r[x] - bx, dyv = r[y] - by;
                float d  = __fmul_rn(__fadd_rn(__fmul_rn(dx, dx), __fmul_rn(dyv, dyv)), 0.5f);
                float s  = (d <= RADIUS) ? 0.0f : sal[(size_t)bb * NPIX + p];
                unsigned long long key =
                    ((unsigned long long)__float_as_uint(d) << 20) | (unsigned)p;
                upd_cand(s, key, fm, fk);
            }
            red_m[tid] = fm; red_k[tid] = fk;
            __syncthreads();
            for (int w = TPB / 2; w > 0; w >>= 1) {
                if (tid < w) upd_cand(red_m[tid + w], red_k[tid + w], red_m[tid], red_k[tid]);
                __syncthreads();
            }
            if (tid == 0) finalize_batch(bb, red_m[0], red_k[0], sal, cur, r, out);
            __syncthreads();
        }
    }
}

// ---------------------------------------------------------------------------
// Kernel C with PDL: prefetches hist before cudaGridDependencySynchronize(),
// then mask = __expf(-(rbf*eps)^2); hist_out = clip(hist*(1-mask), 0, 1).
// 8 floats/thread/iter, outputs via 256-bit STG (halved store count).
// ---------------------------------------------------------------------------
#define C_BPB 256
#define C_NIT 2   // (NPIX/8) / (C_BPB*256)

__global__ void __launch_bounds__(256)
kernelC(const float* __restrict__ hist, const float* __restrict__ grid,
        float* __restrict__ out)
{
    __shared__ __align__(16) float r[NN];
    const int b = blockIdx.y;
    for (int i = threadIdx.x; i < NN; i += 256) r[i] = grid[2*i];

    const float4* h4p = (const float4*)(hist + (size_t)b * NPIX);
    const int base = blockIdx.x * 256 + threadIdx.x;   // 8-float units

    // prefetch hist into registers (input buffer — independent of kernelA);
    // evict-first: kernelC is the last consumer of hist.
    float4 ha[C_NIT], hb2[C_NIT];
    #pragma unroll
    for (int it = 0; it < C_NIT; it++) {
        int v8 = base + it * (C_BPB * 256);
        ha[it]  = __ldcs(&h4p[2*v8]);
        hb2[it] = __ldcs(&h4p[2*v8 + 1]);
    }

    __syncthreads();                    // r[] ready
    cudaGridDependencySynchronize();    // wait for kernelA's results

    const float lx = g_loc[b][0], ly = g_loc[b][1], eps = g_loc[b][2];
    const int anyh = g_anyflag;

    float* hout = out + 32 + (size_t)b * NPIX;
    float* mout = out + 32 + (size_t)BB * NPIX + (size_t)b * NPIX;

    #pragma unroll
    for (int it = 0; it < C_NIT; it++) {
        int v8 = base + it * (C_BPB * 256);
        int p0 = v8 * 8;
        float4 hA = ha[it], hB = hb2[it];
        if (!anyh) { hA = make_float4(1.f,1.f,1.f,1.f); hB = hA; }
        int y = p0 >> 10, x = p0 & 1023;
        float dyl = r[y] - ly;
        float dy2 = __fmul_rn(dyl, dyl);
        float4 ga = *(const float4*)&r[x];
        float4 gb = *(const float4*)&r[x + 4];
        float gx[8] = {ga.x, ga.y, ga.z, ga.w, gb.x, gb.y, gb.z, gb.w};
        float hv[8] = {hA.x, hA.y, hA.z, hA.w, hB.x, hB.y, hB.z, hB.w};
        float m[8], ho[8];
        #pragma unroll
        for (int j = 0; j < 8; j++) {
            float dx  = gx[j] - lx;
            float rbf = __fmul_rn(__fadd_rn(__fmul_rn(dx, dx), dy2), 0.5f);
            float t   = __fmul_rn(rbf, eps);
            float mm  = __expf(-__fmul_rn(t, t));
            m[j]  = mm;
            ho[j] = __saturatef(__fmul_rn(hv[j], 1.0f - mm));
        }
        stg8(hout + p0, ho);
        stg8(mout + p0, m);
    }
}

extern "C" void kernel_launch(void* const* d_in, const int* in_sizes, int n_in,
                              void* d_out, int out_size)
{
    (void)in_sizes; (void)n_in; (void)out_size;
    const float* sal  = (const float*)d_in[0];  // (16,1024,1024)
    const float* hist = (const float*)d_in[1];  // (16,1,1024,1024)
    const float* cur  = (const float*)d_in[2];  // (16,2)
    const float* grid = (const float*)d_in[3];  // (1024,1024,2)
    float* out = (float*)d_out;                 // 32 + 16M (hist) + 16M (mask)

    kernelA<<<dim3(BPB, BB), TPB>>>(sal, hist, cur, grid, out);

    // kernelC via PDL (programmatic stream serialization). Falls back to a
    // plain launch on error.
    cudaLaunchConfig_t cfg = {};
    cfg.gridDim  = dim3(C_BPB, BB);
    cfg.blockDim = dim3(256);
    cudaLaunchAttribute attrs[1];
    attrs[0].id = cudaLaunchAttributeProgrammaticStreamSerialization;
    attrs[0].val.programmaticStreamSerializationAllowed = 1;
    cfg.attrs = attrs;
    cfg.numAttrs = 1;
    cudaError_t e = cudaLaunchKernelEx(&cfg, kernelC, hist, grid, out);
    if (e != cudaSuccess) {
        (void)cudaGetLastError();       // clear, then plain launch
        kernelC<<<dim3(C_BPB, BB), 256>>>(hist, grid, out);
    }
}

// round 17
// speedup vs baseline: 1.0924x; 1.0747x over previous
#include <cuda_runtime.h>
#include <math.h>

#define NN   1024
#define BB   16
#define NPIX (NN*NN)
#define BPB  64      // blocks per batch, kernel A (grid 1024 — proven best)
#define TPB  256
#define NITER 16     // NPIX/4 / (BPB*TPB)

// radius = 1/N^2/2 = 2^-21, exactly representable
#define RADIUS (4.76837158203125e-07f)

__device__ float              g_pm[BB][BPB];   // partial max (masked saliency)
__device__ unsigned long long g_pk[BB][BPB];   // partial key (d_bits<<20 | idx)
__device__ unsigned           g_any[BB*BPB];
__device__ unsigned           g_ctr = 0;
__device__ int                g_anyflag;
__device__ float              g_loc[BB][4];    // lx, ly, eps

__device__ __forceinline__ void upd_cand(float m, unsigned long long k,
                                         float& bm, unsigned long long& bk) {
    bool u = (m > bm) || (m == bm && k < bk);
    if (u) { bm = m; bk = k; }
}

// finalize one batch: compute next_xy + (lx,ly,eps) from the winning candidate
__device__ __forceinline__ void finalize_batch(
    int b, float bm, unsigned long long bk,
    const float* __restrict__ sal, const float* __restrict__ cur,
    const float* __restrict__ r, float* __restrict__ out)
{
    bool allz = (bm == 0.0f);          // masked >= 0 always
    int idx;
    float salv;
    if (allz) {
        idx = 0;                        // argmin of all-inf d -> index 0
        float dx = r[0] - cur[2*b], dyv = r[0] - cur[2*b+1];
        float d00 = __fmul_rn(__fadd_rn(__fmul_rn(dx,dx), __fmul_rn(dyv,dyv)), 0.5f);
        salv = (d00 <= RADIUS) ? 0.0f : sal[(size_t)b * NPIX];
    } else {
        idx  = (int)(bk & 0xFFFFFu);
        salv = sal[(size_t)b * NPIX + idx];   // m>0 => not cur-masked
    }
    int py = idx >> 10, px = idx & 1023;
    float lx = 2.0f * ((float)(px + 1) / 1024.0f) - 1.0f;
    float ly = 2.0f * ((float)(py + 1) / 1024.0f) - 1.0f;
    float sm  = fmaxf(salv, 1e-4f);
    float eps = 10.0f / sm;
    out[2*b]     = allz ? 1.0f : lx;
    out[2*b + 1] = allz ? 1.0f : ly;
    g_loc[b][0] = lx; g_loc[b][1] = ly; g_loc[b][2] = eps;
}

// ---------------------------------------------------------------------------
// Kernel A (R6 loop, grid 1024) with minRegs-forced full occupancy (8 CTA/SM).
// Fused { cur-mask, masked=hist*sal, (max,key) reduce, any-OR }; block-wide
// shared-max gate (stale read = lower bound of final block max, so skipped
// elements can neither win nor tie -> exact). Slow path rare.
// Last block (atomic ticket) finalizes + degenerate hist-all-zero fallback.
// ---------------------------------------------------------------------------
__global__ void __launch_bounds__(TPB, 8)
kernelA(const float* __restrict__ sal, const float* __restrict__ hist,
        const float* __restrict__ cur, const float* __restrict__ grid,
        float* __restrict__ out)
{
    cudaTriggerProgrammaticLaunchCompletion();

    __shared__ __align__(16) float r[NN];
    __shared__ float              red_m[TPB];
    __shared__ unsigned long long red_k[TPB];
    __shared__ unsigned           sh_max;      // block running max (float bits, >=0)
    __shared__ int                lastBlk;

    const int b   = blockIdx.y;
    const int tid = threadIdx.x;

    if (tid == 0) sh_max = 0u;
    for (int i = tid; i < NN; i += TPB) r[i] = grid[2*i];
    __syncthreads();

    const float cx = cur[2*b], cy = cur[2*b+1];
    const float4* sal4 = (const float4*)(sal  + (size_t)b * NPIX);
    const float4* h4p  = (const float4*)(hist + (size_t)b * NPIX);

    float bm = -1.0f; unsigned long long bk = ~0ull;
    unsigned acc = 0u;

    const int base = blockIdx.x * TPB + tid;
    #pragma unroll 4
    for (int it = 0; it < NITER; it++) {
        int v = base + it * (BPB * TPB);
        float4 s4 = __ldcs(&sal4[v]);   // sal never reused -> evict-first
        float4 h4 = h4p[v];             // hist reused by kernelC -> keep in L2
        acc |= (__float_as_uint(h4.x) | __float_as_uint(h4.y) |
                __float_as_uint(h4.z) | __float_as_uint(h4.w));
        float m0 = __fmul_rn(h4.x, s4.x);
        float m1 = __fmul_rn(h4.y, s4.y);
        float m2 = __fmul_rn(h4.z, s4.z);
        float m3 = __fmul_rn(h4.w, s4.w);
        float m4 = fmaxf(fmaxf(m0, m1), fmaxf(m2, m3));
        unsigned stale = sh_max;                    // may be stale: lower bound
        if (__float_as_uint(m4) >= stale) {         // rare after warmup
            int p0 = v * 4;
            int y = p0 >> 10, x = p0 & 1023;
            float dy  = r[y] - cy;
            float dy2 = __fmul_rn(dy, dy);
            float4 gx4 = *(const float4*)&r[x];
            float gx[4] = {gx4.x, gx4.y, gx4.z, gx4.w};
            float sv[4] = {s4.x, s4.y, s4.z, s4.w};
            float hv[4] = {h4.x, h4.y, h4.z, h4.w};
            #pragma unroll
            for (int j = 0; j < 4; j++) {
                float dx = gx[j] - cx;
                float d  = __fmul_rn(__fadd_rn(__fmul_rn(dx, dx), dy2), 0.5f);
                float s  = (d <= RADIUS) ? 0.0f : sv[j];
                float mh = __fmul_rn(hv[j], s);
                unsigned long long key =
                    ((unsigned long long)__float_as_uint(d) << 20) | (unsigned)(p0 + j);
                upd_cand(mh, key, bm, bk);
            }
            if (bm > 0.0f) atomicMax(&sh_max, __float_as_uint(bm));
        }
    }

    red_m[tid] = bm; red_k[tid] = bk;
    int anyv = __syncthreads_or((acc << 1) != 0u);   // <<1 kills -0 sign bits
    for (int w = TPB / 2; w > 0; w >>= 1) {
        if (tid < w) upd_cand(red_m[tid + w], red_k[tid + w], red_m[tid], red_k[tid]);
        __syncthreads();
    }
    if (tid == 0) {
        g_pm[b][blockIdx.x] = red_m[0];
        g_pk[b][blockIdx.x] = red_k[0];
        g_any[b * BPB + blockIdx.x] = anyv ? 1u : 0u;
        __threadfence();
        unsigned old = atomicAdd(&g_ctr, 1u);
        lastBlk = (old == (unsigned)(BPB * BB - 1));
    }
    __syncthreads();
    if (!lastBlk) return;

    // ---- last block: finalization ----
    unsigned a = 0;
    for (int i = tid; i < BB * BPB; i += TPB) a |= g_any[i];
    int anyAll = __syncthreads_or(a != 0u);
    if (tid == 0) { g_anyflag = anyAll; g_ctr = 0; }

    if (anyAll) {
        const int warp = tid >> 5, lane = tid & 31;
        for (int bb = warp; bb < BB; bb += 8) {
            float fm = -1.0f; unsigned long long fk = ~0ull;
            for (int i = lane; i < BPB; i += 32)
                upd_cand(g_pm[bb][i], g_pk[bb][i], fm, fk);
            #pragma unroll
            for (int o = 16; o > 0; o >>= 1) {
                float m2              = __shfl_xor_sync(0xffffffffu, fm, o);
                unsigned long long k2 = __shfl_xor_sync(0xffffffffu, fk, o);
                upd_cand(m2, k2, fm, fk);
            }
            if (lane == 0) finalize_batch(bb, fm, fk, sal, cur, r, out);
        }
    } else {
        // degenerate: whole hist tensor is zero -> hist treated as ones.
        // Slow block-local rescan; never taken for this input, correctness only.
        for (int bb = 0; bb < BB; bb++) {
            const float bx = cur[2*bb], by = cur[2*bb+1];
            float fm = -1.0f; unsigned long long fk = ~0ull;
            for (int p = tid; p < NPIX; p += TPB) {
                int y = p >> 10, x = p & 1023;
                float dx = r[x] - bx, dyv = r[y] - by;
                float d  = __fmul_rn(__fadd_rn(__fmul_rn(dx, dx), __fmul_rn(dyv, dyv)), 0.5f);
                float s  = (d <= RADIUS) ? 0.0f : sal[(size_t)bb * NPIX + p];
                unsigned long long key =
                    ((unsigned long long)__float_as_uint(d) << 20) | (unsigned)p;
                upd_cand(s, key, fm, fk);
            }
            red_m[tid] = fm; red_k[tid] = fk;
            __syncthreads();
            for (int w = TPB / 2; w > 0; w >>= 1) {
                if (tid < w) upd_cand(red_m[tid + w], red_k[tid + w], red_m[tid], red_k[tid]);
                __syncthreads();
            }
            if (tid == 0) finalize_batch(bb, red_m[0], red_k[0], sal, cur, r, out);
            __syncthreads();
        }
    }
}

// ---------------------------------------------------------------------------
// Kernel C with PDL: pre-sync phase loads r[] + prefetches hist (inputs only),
// then cudaGridDependencySynchronize() before consuming g_loc/g_anyflag.
// mask = __expf(-(rbf*eps)^2); hist_out = clip(hist*(1-mask), 0, 1)
// ---------------------------------------------------------------------------
#define C_BPB 256
#define C_NIT 4   // (NPIX/4) / (C_BPB*256)

__global__ void __launch_bounds__(256)
kernelC(const float* __restrict__ hist, const float* __restrict__ grid,
        float* __restrict__ out)
{
    __shared__ __align__(16) float r[NN];
    const int b = blockIdx.y;
    for (int i = threadIdx.x; i < NN; i += 256) r[i] = grid[2*i];

    const float4* h4p = (const float4*)(hist + (size_t)b * NPIX);
    const int base = blockIdx.x * 256 + threadIdx.x;

    // prefetch hist into registers (input buffer — independent of kernelA)
    float4 h4[C_NIT];
    #pragma unroll
    for (int it = 0; it < C_NIT; it++)
        h4[it] = h4p[base + it * (C_BPB * 256)];

    __syncthreads();                    // r[] ready
    cudaGridDependencySynchronize();    // wait for kernelA's results

    const float lx = g_loc[b][0], ly = g_loc[b][1], eps = g_loc[b][2];
    const int anyh = g_anyflag;

    float4* hout = (float4*)(out + 32 + (size_t)b * NPIX);
    float4* mout = (float4*)(out + 32 + (size_t)BB * NPIX + (size_t)b * NPIX);

    #pragma unroll
    for (int it = 0; it < C_NIT; it++) {
        int v = base + it * (C_BPB * 256);
        float4 h = h4[it];
        if (!anyh) h = make_float4(1.f, 1.f, 1.f, 1.f);
        int p0 = v * 4;
        int y = p0 >> 10, x = p0 & 1023;
        float dyl = r[y] - ly;
        float dy2 = __fmul_rn(dyl, dyl);
        float4 gx4 = *(const float4*)&r[x];
        float gx[4] = {gx4.x, gx4.y, gx4.z, gx4.w};
        float hv[4] = {h.x, h.y, h.z, h.w};
        float m[4], ho[4];
        #pragma unroll
        for (int j = 0; j < 4; j++) {
            float dx  = gx[j] - lx;
            float rbf = __fmul_rn(__fadd_rn(__fmul_rn(dx, dx), dy2), 0.5f);
            float t   = __fmul_rn(rbf, eps);
            float mm  = __expf(-__fmul_rn(t, t));
            m[j] = mm;
            float hv2 = __fmul_rn(hv[j], 1.0f - mm);
            ho[j] = __saturatef(hv2);
        }
        __stcs(&hout[v], make_float4(ho[0], ho[1], ho[2], ho[3]));
        __stcs(&mout[v], make_float4(m[0], m[1], m[2], m[3]));
    }
}

extern "C" void kernel_launch(void* const* d_in, const int* in_sizes, int n_in,
                              void* d_out, int out_size)
{
    (void)in_sizes; (void)n_in; (void)out_size;
    const float* sal  = (const float*)d_in[0];  // (16,1024,1024)
    const float* hist = (const float*)d_in[1];  // (16,1,1024,1024)
    const float* cur  = (const float*)d_in[2];  // (16,2)
    const float* grid = (const float*)d_in[3];  // (1024,1024,2)
    float* out = (float*)d_out;                 // 32 + 16M (hist) + 16M (mask)

    kernelA<<<dim3(BPB, BB), TPB>>>(sal, hist, cur, grid, out);

    // kernelC via PDL (programmatic stream serialization). Falls back to a
    // plain launch on error.
    cudaLaunchConfig_t cfg = {};
    cfg.gridDim  = dim3(C_BPB, BB);
    cfg.blockDim = dim3(256);
    cudaLaunchAttribute attrs[1];
    attrs[0].id = cudaLaunchAttributeProgrammaticStreamSerialization;
    attrs[0].val.programmaticStreamSerializationAllowed = 1;
    cfg.attrs = attrs;
    cfg.numAttrs = 1;
    cudaError_t e = cudaLaunchKernelEx(&cfg, kernelC, hist, grid, out);
    if (e != cudaSuccess) {
        (void)cudaGetLastError();       // clear, then plain launch
        kernelC<<<dim3(C_BPB, BB), 256>>>(hist, grid, out);
    }
}